// round 7
// baseline (speedup 1.0000x reference)
#include <cuda_runtime.h>
#include <cuda_bf16.h>

#define NN 100000
#define NE 1600000
#define HF 64
#define FULL 0xFFFFFFFFu

#define SB   512
#define NBLK ((NN + SB - 1) / SB)   // 196

#define C0N 50048                    // chunk 0 node count (multiple of 64)
#define C1N (NN - C0N)               // chunk 1 node count

// ---------------- scratch (device globals; no allocation allowed) ----------
__device__ float g_h  [NN * HF];   // h for layers 1 & 3
__device__ float g_h2 [NN * HF];   // h for layer 2 (overlap double-buffer)
__device__ float g_nf [NN * HF];
__device__ float g_nf2[NN * HF];
__device__ float g_el [NN], g_er [NN];    // layers 1 & 3
__device__ float g_el2[NN], g_er2[NN];    // layer 2
// CSR-by-dst
__device__ int g_cnt   [NN];
__device__ int g_incl  [NN];
__device__ int g_bsum  [NBLK];
__device__ int g_boff  [NBLK];
__device__ int g_rowptr[NN + 1];
__device__ int g_cursor[NN];
__device__ int g_csrc  [NE];

// ============================ CSR build =====================================
__global__ void csr_zero(int* __restrict__ cnt) {
    int i = blockIdx.x * blockDim.x + threadIdx.x;
    if (i < NN) cnt[i] = 0;
}

__global__ void csr_hist(const int* __restrict__ dst, int* __restrict__ cnt) {
    int e = blockIdx.x * blockDim.x + threadIdx.x;
    if (e < NE) atomicAdd(&cnt[dst[e]], 1);
}

__global__ void csr_scan1(const int* __restrict__ cnt, int* __restrict__ incl,
                          int* __restrict__ bsum) {
    __shared__ int wsum[16];
    int tid = threadIdx.x, lane = tid & 31, wid = tid >> 5;
    int i = blockIdx.x * SB + tid;
    int v = (i < NN) ? cnt[i] : 0;
    int x = v;
    #pragma unroll
    for (int o = 1; o < 32; o <<= 1) {
        int t = __shfl_up_sync(FULL, x, o);
        if (lane >= o) x += t;
    }
    if (lane == 31) wsum[wid] = x;
    __syncthreads();
    if (wid == 0) {
        int w = (lane < 16) ? wsum[lane] : 0;
        #pragma unroll
        for (int o = 1; o < 16; o <<= 1) {
            int t = __shfl_up_sync(FULL, w, o);
            if (lane >= o) w += t;
        }
        if (lane < 16) wsum[lane] = w;
    }
    __syncthreads();
    int inc = x + (wid > 0 ? wsum[wid - 1] : 0);
    if (i < NN) incl[i] = inc;
    if (tid == SB - 1) bsum[blockIdx.x] = inc;
}

__global__ void csr_scan2(const int* __restrict__ bsum, int* __restrict__ boff) {
    __shared__ int wsum[8];
    int tid = threadIdx.x, lane = tid & 31, wid = tid >> 5;
    int v = (tid < NBLK) ? bsum[tid] : 0;
    int x = v;
    #pragma unroll
    for (int o = 1; o < 32; o <<= 1) {
        int t = __shfl_up_sync(FULL, x, o);
        if (lane >= o) x += t;
    }
    if (lane == 31) wsum[wid] = x;
    __syncthreads();
    if (wid == 0) {
        int w = (lane < 8) ? wsum[lane] : 0;
        #pragma unroll
        for (int o = 1; o < 8; o <<= 1) {
            int t = __shfl_up_sync(FULL, w, o);
            if (lane >= o) w += t;
        }
        if (lane < 8) wsum[lane] = w;
    }
    __syncthreads();
    int inc = x + (wid > 0 ? wsum[wid - 1] : 0);
    if (tid < NBLK) boff[tid] = inc - v;
}

__global__ void csr_scan3(const int* __restrict__ cnt, const int* __restrict__ incl,
                          const int* __restrict__ boff, int* __restrict__ rowptr,
                          int* __restrict__ cursor) {
    int b = blockIdx.x;
    int i = b * SB + threadIdx.x;
    if (i < NN) {
        int ex = incl[i] - cnt[i] + boff[b];
        rowptr[i] = ex;
        cursor[i] = ex;
    }
    if (i == 0) rowptr[NN] = NE;
}

__global__ void csr_fill(const int* __restrict__ src, const int* __restrict__ dst,
                         int* __restrict__ cursor, int* __restrict__ csrc) {
    int e = blockIdx.x * blockDim.x + threadIdx.x;
    if (e >= NE) return;
    int p = atomicAdd(&cursor[dst[e]], 1);
    csrc[p] = src[e];
}

// ============================ GEMM (+ el/er) ================================
// R4 version: 64x64 tile / 256 threads / 4x4 subtile, coalesced staging.
// row_base/row_count select a node chunk (base multiple of 64).
template <int K>
__global__ void __launch_bounds__(256)
gemm_el_er(const float* __restrict__ x, const float* __restrict__ W,
           const float* __restrict__ al, const float* __restrict__ ar,
           float* __restrict__ h, float* __restrict__ el, float* __restrict__ er,
           int row_base, int row_count) {
    __shared__ float sx[64][68];
    __shared__ float sW[64][64];

    int tid = threadIdx.x;
    int base  = row_base + blockIdx.x * 64;
    int limit = row_base + row_count;
    int tx = tid & 15, ty = tid >> 4;
    int c0 = tx * 4, r0 = ty * 4;

    float acc[4][4];
    #pragma unroll
    for (int j = 0; j < 4; j++)
        #pragma unroll
        for (int q = 0; q < 4; q++) acc[j][q] = 0.0f;

    for (int kc = 0; kc < K; kc += 64) {
        if (kc) __syncthreads();
        #pragma unroll
        for (int i = tid; i < 64 * 16; i += 256) {
            int r = i >> 4, q = i & 15;
            int row = base + r;
            float4 v = make_float4(0.f, 0.f, 0.f, 0.f);
            if (row < limit) v = *(const float4*)&x[row * K + kc + q * 4];
            *(float4*)&sx[r][q * 4] = v;
        }
        #pragma unroll
        for (int i = tid; i < 64 * 16; i += 256) {
            int k = i >> 4, q = i & 15;
            *(float4*)&sW[k][q * 4] = *(const float4*)&W[(kc + k) * HF + q * 4];
        }
        __syncthreads();

        #pragma unroll 4
        for (int k = 0; k < 64; k++) {
            float4 w4 = *(const float4*)&sW[k][c0];
            #pragma unroll
            for (int j = 0; j < 4; j++) {
                float xv = sx[r0 + j][k];
                acc[j][0] = fmaf(xv, w4.x, acc[j][0]);
                acc[j][1] = fmaf(xv, w4.y, acc[j][1]);
                acc[j][2] = fmaf(xv, w4.z, acc[j][2]);
                acc[j][3] = fmaf(xv, w4.w, acc[j][3]);
            }
        }
    }

    float4 al4 = *(const float4*)&al[c0];
    float4 ar4 = *(const float4*)&ar[c0];
    #pragma unroll
    for (int j = 0; j < 4; j++) {
        int g = base + r0 + j;
        bool ok = g < limit;
        if (ok) *(float4*)&h[g * HF + c0] =
            make_float4(acc[j][0], acc[j][1], acc[j][2], acc[j][3]);
        float pel = acc[j][0] * al4.x + acc[j][1] * al4.y
                  + acc[j][2] * al4.z + acc[j][3] * al4.w;
        float per = acc[j][0] * ar4.x + acc[j][1] * ar4.y
                  + acc[j][2] * ar4.z + acc[j][3] * ar4.w;
        #pragma unroll
        for (int o = 8; o > 0; o >>= 1) {
            pel += __shfl_xor_sync(FULL, pel, o);
            per += __shfl_xor_sync(FULL, per, o);
        }
        if (tx == 0 && ok) { el[g] = pel; er[g] = per; }
    }
}

// ============== fused per-node softmax + aggregate + bias + relu ============
// Warp per dst node; 4 accumulator pairs, 4 edges per gather step (MLP 4).
__global__ void __launch_bounds__(256)
gat_aggregate(const int* __restrict__ rowptr, const int* __restrict__ csrc,
              const float* __restrict__ el, const float* __restrict__ er,
              const float* __restrict__ h, const float* __restrict__ b,
              float* __restrict__ y, int node_base, int node_count) {
    int idx = (blockIdx.x * blockDim.x + threadIdx.x) >> 5;
    if (idx >= node_count) return;
    int node = node_base + idx;
    int lane = threadIdx.x & 31;

    int beg = rowptr[node], end = rowptr[node + 1];
    float erd = er[node];

    float m = -__int_as_float(0x7F800000);
    float s = 0.0f;
    float aA0 = 0.f, aA1 = 0.f, aB0 = 0.f, aB1 = 0.f;
    float aC0 = 0.f, aC1 = 0.f, aD0 = 0.f, aD1 = 0.f;
    int c = 2 * lane;

    for (int base = beg; base < end; base += 32) {
        int ii = base + lane;
        bool valid = ii < end;
        int sn = valid ? csrc[ii] : 0;
        float v;
        if (valid) {
            v = el[sn] + erd;
            v = v > 0.0f ? v : 0.2f * v;
        } else {
            v = -__int_as_float(0x7F800000);
        }
        float gm = v;
        #pragma unroll
        for (int o = 16; o > 0; o >>= 1)
            gm = fmaxf(gm, __shfl_xor_sync(FULL, gm, o));
        float mnew = fmaxf(m, gm);
        float scale = __expf(m - mnew);
        s *= scale;
        aA0 *= scale; aA1 *= scale; aB0 *= scale; aB1 *= scale;
        aC0 *= scale; aC1 *= scale; aD0 *= scale; aD1 *= scale;
        m = mnew;

        float w = valid ? __expf(v - mnew) : 0.0f;
        float ws = w;
        #pragma unroll
        for (int o = 16; o > 0; o >>= 1)
            ws += __shfl_xor_sync(FULL, ws, o);
        s += ws;

        int cnt = end - base; if (cnt > 32) cnt = 32;
        int j = 0;
        for (; j + 3 < cnt; j += 4) {
            int   s0 = __shfl_sync(FULL, sn, j);
            int   s1 = __shfl_sync(FULL, sn, j + 1);
            int   s2 = __shfl_sync(FULL, sn, j + 2);
            int   s3 = __shfl_sync(FULL, sn, j + 3);
            float w0 = __shfl_sync(FULL, w, j);
            float w1 = __shfl_sync(FULL, w, j + 1);
            float w2 = __shfl_sync(FULL, w, j + 2);
            float w3 = __shfl_sync(FULL, w, j + 3);
            float2 h0 = *(const float2*)&h[s0 * HF + c];
            float2 h1 = *(const float2*)&h[s1 * HF + c];
            float2 h2 = *(const float2*)&h[s2 * HF + c];
            float2 h3 = *(const float2*)&h[s3 * HF + c];
            aA0 = fmaf(w0, h0.x, aA0); aA1 = fmaf(w0, h0.y, aA1);
            aB0 = fmaf(w1, h1.x, aB0); aB1 = fmaf(w1, h1.y, aB1);
            aC0 = fmaf(w2, h2.x, aC0); aC1 = fmaf(w2, h2.y, aC1);
            aD0 = fmaf(w3, h3.x, aD0); aD1 = fmaf(w3, h3.y, aD1);
        }
        for (; j < cnt; j++) {
            int   s0 = __shfl_sync(FULL, sn, j);
            float w0 = __shfl_sync(FULL, w, j);
            float2 h0 = *(const float2*)&h[s0 * HF + c];
            aA0 = fmaf(w0, h0.x, aA0); aA1 = fmaf(w0, h0.y, aA1);
        }
    }

    float inv = (end > beg) ? __fdividef(1.0f, s) : 0.0f;
    float o0 = ((aA0 + aB0) + (aC0 + aD0)) * inv + b[c];
    float o1 = ((aA1 + aB1) + (aC1 + aD1)) * inv + b[c + 1];
    o0 = o0 > 0.0f ? o0 : 0.0f;
    o1 = o1 > 0.0f ? o1 : 0.0f;
    *(float2*)&y[node * HF + c] = make_float2(o0, o1);
}

// ============================ host driver ===================================
static inline int agg_grid(int nodes) { return (nodes * 32 + 255) / 256; }
static inline int gemm_grid(int rows) { return (rows + 63) / 64; }

extern "C" void kernel_launch(void* const* d_in, const int* in_sizes, int n_in,
                              void* d_out, int out_size) {
    const float* x   = (const float*)d_in[0];
    const int*   src = (const int*)  d_in[1];
    const int*   dst = (const int*)  d_in[2];
    const float* W1  = (const float*)d_in[3];
    const float* al1 = (const float*)d_in[4];
    const float* ar1 = (const float*)d_in[5];
    const float* b1  = (const float*)d_in[6];
    const float* W2  = (const float*)d_in[7];
    const float* al2 = (const float*)d_in[8];
    const float* ar2 = (const float*)d_in[9];
    const float* b2  = (const float*)d_in[10];
    const float* W3  = (const float*)d_in[11];
    const float* al3 = (const float*)d_in[12];
    const float* ar3 = (const float*)d_in[13];
    const float* b3  = (const float*)d_in[14];
    float* out = (float*)d_out;

    float *h, *h2, *nf, *nf2, *el, *er, *el2, *er2;
    int *cnt, *incl, *bsum, *boff, *rowptr, *cursor, *csrc;
    cudaGetSymbolAddress((void**)&h,      g_h);
    cudaGetSymbolAddress((void**)&h2,     g_h2);
    cudaGetSymbolAddress((void**)&nf,     g_nf);
    cudaGetSymbolAddress((void**)&nf2,    g_nf2);
    cudaGetSymbolAddress((void**)&el,     g_el);
    cudaGetSymbolAddress((void**)&er,     g_er);
    cudaGetSymbolAddress((void**)&el2,    g_el2);
    cudaGetSymbolAddress((void**)&er2,    g_er2);
    cudaGetSymbolAddress((void**)&cnt,    g_cnt);
    cudaGetSymbolAddress((void**)&incl,   g_incl);
    cudaGetSymbolAddress((void**)&bsum,   g_bsum);
    cudaGetSymbolAddress((void**)&boff,   g_boff);
    cudaGetSymbolAddress((void**)&rowptr, g_rowptr);
    cudaGetSymbolAddress((void**)&cursor, g_cursor);
    cudaGetSymbolAddress((void**)&csrc,   g_csrc);

    static cudaStream_t s2 = nullptr;
    static cudaEvent_t ev[8];
    if (!s2) {
        cudaStreamCreateWithFlags(&s2, cudaStreamNonBlocking);
        for (int i = 0; i < 8; i++)
            cudaEventCreateWithFlags(&ev[i], cudaEventDisableTiming);
    }

    // ---- fork: CSR build on s2, layer-1 GEMM on main ----
    cudaEventRecord(ev[0], 0);
    cudaStreamWaitEvent(s2, ev[0], 0);
    csr_zero<<<(NN + 255) / 256, 256, 0, s2>>>(cnt);
    csr_hist<<<(NE + 255) / 256, 256, 0, s2>>>(dst, cnt);
    csr_scan1<<<NBLK, SB, 0, s2>>>(cnt, incl, bsum);
    csr_scan2<<<1, 256, 0, s2>>>(bsum, boff);
    csr_scan3<<<NBLK, SB, 0, s2>>>(cnt, incl, boff, rowptr, cursor);
    csr_fill<<<(NE + 255) / 256, 256, 0, s2>>>(src, dst, cursor, csrc);
    cudaEventRecord(ev[1], s2);

    gemm_el_er<128><<<gemm_grid(NN), 256>>>(x, W1, al1, ar1, h, el, er, 0, NN);
    cudaStreamWaitEvent(0, ev[1], 0);

    // ---- layer 1 aggregate in 2 chunks; gemm2 chunks chase on s2 ----
    gat_aggregate<<<agg_grid(C0N), 256>>>(rowptr, csrc, el, er, h, b1, nf, 0, C0N);
    cudaEventRecord(ev[2], 0);
    gat_aggregate<<<agg_grid(C1N), 256>>>(rowptr, csrc, el, er, h, b1, nf, C0N, C1N);
    cudaEventRecord(ev[3], 0);

    cudaStreamWaitEvent(s2, ev[2], 0);
    gemm_el_er<64><<<gemm_grid(C0N), 256, 0, s2>>>(nf, W2, al2, ar2, h2, el2, er2, 0, C0N);
    cudaStreamWaitEvent(s2, ev[3], 0);
    gemm_el_er<64><<<gemm_grid(C1N), 256, 0, s2>>>(nf, W2, al2, ar2, h2, el2, er2, C0N, C1N);
    cudaEventRecord(ev[4], s2);

    // ---- layer 2 aggregate in 2 chunks; gemm3 chunks chase on s2 ----
    cudaStreamWaitEvent(0, ev[4], 0);
    gat_aggregate<<<agg_grid(C0N), 256>>>(rowptr, csrc, el2, er2, h2, b2, nf2, 0, C0N);
    cudaEventRecord(ev[5], 0);
    gat_aggregate<<<agg_grid(C1N), 256>>>(rowptr, csrc, el2, er2, h2, b2, nf2, C0N, C1N);
    cudaEventRecord(ev[6], 0);

    cudaStreamWaitEvent(s2, ev[5], 0);
    gemm_el_er<64><<<gemm_grid(C0N), 256, 0, s2>>>(nf2, W3, al3, ar3, h, el, er, 0, C0N);
    cudaStreamWaitEvent(s2, ev[6], 0);
    gemm_el_er<64><<<gemm_grid(C1N), 256, 0, s2>>>(nf2, W3, al3, ar3, h, el, er, C0N, C1N);
    cudaEventRecord(ev[7], s2);

    // ---- layer 3 aggregate -> out ----
    cudaStreamWaitEvent(0, ev[7], 0);
    gat_aggregate<<<agg_grid(NN), 256>>>(rowptr, csrc, el, er, h, b3, out, 0, NN);
}

// round 8
// speedup vs baseline: 1.0929x; 1.0929x over previous
#include <cuda_runtime.h>
#include <cuda_bf16.h>

#define NN 100000
#define NE 1600000
#define HF 64
#define FULL 0xFFFFFFFFu

#define SB   512
#define NBLK ((NN + SB - 1) / SB)   // 196

// ---------------- scratch (device globals; no allocation allowed) ----------
__device__ float g_h  [NN * HF];
__device__ float g_nf [NN * HF];
__device__ float g_nf2[NN * HF];
__device__ float g_el [NN];
__device__ float g_er [NN];
// CSR-by-dst
__device__ int g_cnt   [NN];
__device__ int g_incl  [NN];
__device__ int g_bsum  [NBLK];
__device__ int g_boff  [NBLK];
__device__ int g_rowptr[NN + 1];
__device__ int g_cursor[NN];
__device__ int g_csrc  [NE];

// ============================ CSR build =====================================
__global__ void csr_zero(int* __restrict__ cnt) {
    int i = blockIdx.x * blockDim.x + threadIdx.x;
    if (i < NN) cnt[i] = 0;
}

__global__ void csr_hist(const int* __restrict__ dst, int* __restrict__ cnt) {
    int e = blockIdx.x * blockDim.x + threadIdx.x;
    if (e < NE) atomicAdd(&cnt[dst[e]], 1);
}

__global__ void csr_scan1(const int* __restrict__ cnt, int* __restrict__ incl,
                          int* __restrict__ bsum) {
    __shared__ int wsum[16];
    int tid = threadIdx.x, lane = tid & 31, wid = tid >> 5;
    int i = blockIdx.x * SB + tid;
    int v = (i < NN) ? cnt[i] : 0;
    int x = v;
    #pragma unroll
    for (int o = 1; o < 32; o <<= 1) {
        int t = __shfl_up_sync(FULL, x, o);
        if (lane >= o) x += t;
    }
    if (lane == 31) wsum[wid] = x;
    __syncthreads();
    if (wid == 0) {
        int w = (lane < 16) ? wsum[lane] : 0;
        #pragma unroll
        for (int o = 1; o < 16; o <<= 1) {
            int t = __shfl_up_sync(FULL, w, o);
            if (lane >= o) w += t;
        }
        if (lane < 16) wsum[lane] = w;
    }
    __syncthreads();
    int inc = x + (wid > 0 ? wsum[wid - 1] : 0);
    if (i < NN) incl[i] = inc;
    if (tid == SB - 1) bsum[blockIdx.x] = inc;
}

__global__ void csr_scan2(const int* __restrict__ bsum, int* __restrict__ boff) {
    __shared__ int wsum[8];
    int tid = threadIdx.x, lane = tid & 31, wid = tid >> 5;
    int v = (tid < NBLK) ? bsum[tid] : 0;
    int x = v;
    #pragma unroll
    for (int o = 1; o < 32; o <<= 1) {
        int t = __shfl_up_sync(FULL, x, o);
        if (lane >= o) x += t;
    }
    if (lane == 31) wsum[wid] = x;
    __syncthreads();
    if (wid == 0) {
        int w = (lane < 8) ? wsum[lane] : 0;
        #pragma unroll
        for (int o = 1; o < 8; o <<= 1) {
            int t = __shfl_up_sync(FULL, w, o);
            if (lane >= o) w += t;
        }
        if (lane < 8) wsum[lane] = w;
    }
    __syncthreads();
    int inc = x + (wid > 0 ? wsum[wid - 1] : 0);
    if (tid < NBLK) boff[tid] = inc - v;
}

__global__ void csr_scan3(const int* __restrict__ cnt, const int* __restrict__ incl,
                          const int* __restrict__ boff, int* __restrict__ rowptr,
                          int* __restrict__ cursor) {
    int b = blockIdx.x;
    int i = b * SB + threadIdx.x;
    if (i < NN) {
        int ex = incl[i] - cnt[i] + boff[b];
        rowptr[i] = ex;
        cursor[i] = ex;
    }
    if (i == 0) rowptr[NN] = NE;
}

__global__ void csr_fill(const int* __restrict__ src, const int* __restrict__ dst,
                         int* __restrict__ cursor, int* __restrict__ csrc) {
    int e = blockIdx.x * blockDim.x + threadIdx.x;
    if (e >= NE) return;
    int p = atomicAdd(&cursor[dst[e]], 1);
    csrc[p] = src[e];
}

// ==================== tensor-core GEMM (+ el/er), bf16 3-split ==============
// D = x@W in fp32-grade precision: x=xh+xl, W=Wh+Wl (bf16 splits),
// D = xh*Wh + xh*Wl + xl*Wh  (xl*Wl ~2^-18, dropped).
// Block: 128 rows x 64 cols, 8 warps, warp w owns rows [16w,16w+16).
// K chunked by 32; smem A split + W-transposed split, pad 4 (conflict-free).

#define KS 32
#define XP (KS + 4)

#define MMA_BF16(C, A0, A1, A2, A3, B0, B1)                              \
    asm volatile(                                                        \
        "mma.sync.aligned.m16n8k16.row.col.f32.bf16.bf16.f32 "           \
        "{%0,%1,%2,%3}, {%4,%5,%6,%7}, {%8,%9}, {%0,%1,%2,%3};\n"        \
        : "+f"(C[0]), "+f"(C[1]), "+f"(C[2]), "+f"(C[3])                 \
        : "r"(A0), "r"(A1), "r"(A2), "r"(A3), "r"(B0), "r"(B1))

__device__ __forceinline__ unsigned ldsm_u32(const __nv_bfloat16* p) {
    return *reinterpret_cast<const unsigned*>(p);
}

template <int K>
__global__ void __launch_bounds__(256)
gemm_el_er(const float* __restrict__ x, const float* __restrict__ W,
           const float* __restrict__ al, const float* __restrict__ ar,
           float* __restrict__ h, float* __restrict__ el, float* __restrict__ er) {
    __shared__ __nv_bfloat16 sxh[128][XP];
    __shared__ __nv_bfloat16 sxl[128][XP];
    __shared__ __nv_bfloat16 swh[64][XP];
    __shared__ __nv_bfloat16 swl[64][XP];

    int tid = threadIdx.x;
    int warp = tid >> 5, lane = tid & 31;
    int g = lane >> 2, q = lane & 3;
    int base = blockIdx.x * 128;

    float c[8][4];
    #pragma unroll
    for (int nt = 0; nt < 8; nt++)
        #pragma unroll
        for (int i = 0; i < 4; i++) c[nt][i] = 0.0f;

    for (int kc = 0; kc < K; kc += KS) {
        if (kc) __syncthreads();
        // stage x chunk: 128 rows x 32 k, split to bf16 hi/lo
        #pragma unroll
        for (int it = 0; it < 4; it++) {
            int idx = tid + it * 256;        // 0..1023
            int r = idx >> 3, qq = idx & 7;
            int row = base + r;
            float4 v = make_float4(0.f, 0.f, 0.f, 0.f);
            if (row < NN) v = *(const float4*)&x[row * K + kc + qq * 4];
            float vv[4] = {v.x, v.y, v.z, v.w};
            #pragma unroll
            for (int e = 0; e < 4; e++) {
                __nv_bfloat16 hi = __float2bfloat16(vv[e]);
                __nv_bfloat16 lo = __float2bfloat16(vv[e] - __bfloat162float(hi));
                sxh[r][qq * 4 + e] = hi;
                sxl[r][qq * 4 + e] = lo;
            }
        }
        // stage W chunk transposed: swT[n][k], split hi/lo
        #pragma unroll
        for (int it = 0; it < 2; it++) {
            int idx = tid + it * 256;        // 0..511
            int k = idx >> 4, qq = idx & 15;
            float4 v = *(const float4*)&W[(kc + k) * HF + qq * 4];
            float vv[4] = {v.x, v.y, v.z, v.w};
            #pragma unroll
            for (int e = 0; e < 4; e++) {
                __nv_bfloat16 hi = __float2bfloat16(vv[e]);
                __nv_bfloat16 lo = __float2bfloat16(vv[e] - __bfloat162float(hi));
                swh[qq * 4 + e][k] = hi;
                swl[qq * 4 + e][k] = lo;
            }
        }
        __syncthreads();

        #pragma unroll
        for (int ks = 0; ks < KS / 16; ks++) {
            int k16 = ks * 16;
            int r1 = warp * 16 + g;
            int ka = k16 + q * 2;
            unsigned ah0 = ldsm_u32(&sxh[r1][ka]);
            unsigned ah1 = ldsm_u32(&sxh[r1 + 8][ka]);
            unsigned ah2 = ldsm_u32(&sxh[r1][ka + 8]);
            unsigned ah3 = ldsm_u32(&sxh[r1 + 8][ka + 8]);
            unsigned alo0 = ldsm_u32(&sxl[r1][ka]);
            unsigned alo1 = ldsm_u32(&sxl[r1 + 8][ka]);
            unsigned alo2 = ldsm_u32(&sxl[r1][ka + 8]);
            unsigned alo3 = ldsm_u32(&sxl[r1 + 8][ka + 8]);
            #pragma unroll
            for (int nt = 0; nt < 8; nt++) {
                int n = nt * 8 + g;
                unsigned bh0 = ldsm_u32(&swh[n][ka]);
                unsigned bh1 = ldsm_u32(&swh[n][ka + 8]);
                unsigned bl0 = ldsm_u32(&swl[n][ka]);
                unsigned bl1 = ldsm_u32(&swl[n][ka + 8]);
                MMA_BF16(c[nt], ah0, ah1, ah2, ah3, bh0, bh1);
                MMA_BF16(c[nt], ah0, ah1, ah2, ah3, bl0, bl1);
                MMA_BF16(c[nt], alo0, alo1, alo2, alo3, bh0, bh1);
            }
        }
    }

    // epilogue: store h rows, fused el/er
    int gr1 = base + warp * 16 + g;
    int gr2 = gr1 + 8;
    float pel1 = 0.f, per1 = 0.f, pel2 = 0.f, per2 = 0.f;
    #pragma unroll
    for (int nt = 0; nt < 8; nt++) {
        int col = nt * 8 + q * 2;
        float2 a2 = *(const float2*)&al[col];
        float2 r2 = *(const float2*)&ar[col];
        pel1 += c[nt][0] * a2.x + c[nt][1] * a2.y;
        per1 += c[nt][0] * r2.x + c[nt][1] * r2.y;
        pel2 += c[nt][2] * a2.x + c[nt][3] * a2.y;
        per2 += c[nt][2] * r2.x + c[nt][3] * r2.y;
        if (gr1 < NN) *(float2*)&h[gr1 * HF + col] = make_float2(c[nt][0], c[nt][1]);
        if (gr2 < NN) *(float2*)&h[gr2 * HF + col] = make_float2(c[nt][2], c[nt][3]);
    }
    #pragma unroll
    for (int o = 1; o <= 2; o <<= 1) {   // reduce over q within the quad
        pel1 += __shfl_xor_sync(FULL, pel1, o);
        per1 += __shfl_xor_sync(FULL, per1, o);
        pel2 += __shfl_xor_sync(FULL, pel2, o);
        per2 += __shfl_xor_sync(FULL, per2, o);
    }
    if (q == 0) {
        if (gr1 < NN) { el[gr1] = pel1; er[gr1] = per1; }
        if (gr2 < NN) { el[gr2] = pel2; er[gr2] = per2; }
    }
}

// ============== fused per-node softmax + aggregate + bias + relu ============
__global__ void __launch_bounds__(256)
gat_aggregate(const int* __restrict__ rowptr, const int* __restrict__ csrc,
              const float* __restrict__ el, const float* __restrict__ er,
              const float* __restrict__ h, const float* __restrict__ b,
              float* __restrict__ y) {
    int gwarp = (blockIdx.x * blockDim.x + threadIdx.x) >> 5;
    if (gwarp >= NN) return;
    int lane = threadIdx.x & 31;

    int beg = rowptr[gwarp], end = rowptr[gwarp + 1];
    float erd = er[gwarp];

    float m = -__int_as_float(0x7F800000);
    float s = 0.0f;
    float a0A = 0.0f, a1A = 0.0f, a0B = 0.0f, a1B = 0.0f;
    int c = 2 * lane;

    for (int base = beg; base < end; base += 32) {
        int idx = base + lane;
        bool valid = idx < end;
        int sn = valid ? csrc[idx] : 0;
        float v;
        if (valid) {
            v = el[sn] + erd;
            v = v > 0.0f ? v : 0.2f * v;
        } else {
            v = -__int_as_float(0x7F800000);
        }
        float gm = v;
        #pragma unroll
        for (int o = 16; o > 0; o >>= 1)
            gm = fmaxf(gm, __shfl_xor_sync(FULL, gm, o));
        float mnew = fmaxf(m, gm);
        float scale = __expf(m - mnew);
        s *= scale; a0A *= scale; a1A *= scale; a0B *= scale; a1B *= scale;
        m = mnew;

        float w = valid ? __expf(v - mnew) : 0.0f;
        float ws = w;
        #pragma unroll
        for (int o = 16; o > 0; o >>= 1)
            ws += __shfl_xor_sync(FULL, ws, o);
        s += ws;

        int cnt = end - base; if (cnt > 32) cnt = 32;
        int j = 0;
        #pragma unroll 2
        for (; j + 1 < cnt; j += 2) {
            int   s0 = __shfl_sync(FULL, sn, j);
            float w0 = __shfl_sync(FULL, w,  j);
            int   s1 = __shfl_sync(FULL, sn, j + 1);
            float w1 = __shfl_sync(FULL, w,  j + 1);
            float2 h0 = *(const float2*)&h[s0 * HF + c];
            float2 h1 = *(const float2*)&h[s1 * HF + c];
            a0A = fmaf(w0, h0.x, a0A); a1A = fmaf(w0, h0.y, a1A);
            a0B = fmaf(w1, h1.x, a0B); a1B = fmaf(w1, h1.y, a1B);
        }
        if (j < cnt) {
            int   s0 = __shfl_sync(FULL, sn, j);
            float w0 = __shfl_sync(FULL, w,  j);
            float2 h0 = *(const float2*)&h[s0 * HF + c];
            a0A = fmaf(w0, h0.x, a0A); a1A = fmaf(w0, h0.y, a1A);
        }
    }

    float inv = (end > beg) ? __fdividef(1.0f, s) : 0.0f;
    float o0 = (a0A + a0B) * inv + b[c];
    float o1 = (a1A + a1B) * inv + b[c + 1];
    o0 = o0 > 0.0f ? o0 : 0.0f;
    o1 = o1 > 0.0f ? o1 : 0.0f;
    *(float2*)&y[gwarp * HF + c] = make_float2(o0, o1);
}

// ============================ host driver ===================================
extern "C" void kernel_launch(void* const* d_in, const int* in_sizes, int n_in,
                              void* d_out, int out_size) {
    const float* x   = (const float*)d_in[0];
    const int*   src = (const int*)  d_in[1];
    const int*   dst = (const int*)  d_in[2];
    const float* W1  = (const float*)d_in[3];
    const float* al1 = (const float*)d_in[4];
    const float* ar1 = (const float*)d_in[5];
    const float* b1  = (const float*)d_in[6];
    const float* W2  = (const float*)d_in[7];
    const float* al2 = (const float*)d_in[8];
    const float* ar2 = (const float*)d_in[9];
    const float* b2  = (const float*)d_in[10];
    const float* W3  = (const float*)d_in[11];
    const float* al3 = (const float*)d_in[12];
    const float* ar3 = (const float*)d_in[13];
    const float* b3  = (const float*)d_in[14];
    float* out = (float*)d_out;

    float *h, *nf, *nf2, *el, *er;
    int *cnt, *incl, *bsum, *boff, *rowptr, *cursor, *csrc;
    cudaGetSymbolAddress((void**)&h,      g_h);
    cudaGetSymbolAddress((void**)&nf,     g_nf);
    cudaGetSymbolAddress((void**)&nf2,    g_nf2);
    cudaGetSymbolAddress((void**)&el,     g_el);
    cudaGetSymbolAddress((void**)&er,     g_er);
    cudaGetSymbolAddress((void**)&cnt,    g_cnt);
    cudaGetSymbolAddress((void**)&incl,   g_incl);
    cudaGetSymbolAddress((void**)&bsum,   g_bsum);
    cudaGetSymbolAddress((void**)&boff,   g_boff);
    cudaGetSymbolAddress((void**)&rowptr, g_rowptr);
    cudaGetSymbolAddress((void**)&cursor, g_cursor);
    cudaGetSymbolAddress((void**)&csrc,   g_csrc);

    static cudaStream_t s2 = nullptr;
    static cudaEvent_t evFork = nullptr, evJoin = nullptr;
    if (!s2) {
        cudaStreamCreateWithFlags(&s2, cudaStreamNonBlocking);
        cudaEventCreateWithFlags(&evFork, cudaEventDisableTiming);
        cudaEventCreateWithFlags(&evJoin, cudaEventDisableTiming);
    }

    // ---- fork: CSR build on s2, layer-1 GEMM on main stream ----
    cudaEventRecord(evFork, 0);
    cudaStreamWaitEvent(s2, evFork, 0);
    csr_zero<<<(NN + 255) / 256, 256, 0, s2>>>(cnt);
    csr_hist<<<(NE + 255) / 256, 256, 0, s2>>>(dst, cnt);
    csr_scan1<<<NBLK, SB, 0, s2>>>(cnt, incl, bsum);
    csr_scan2<<<1, 256, 0, s2>>>(bsum, boff);
    csr_scan3<<<NBLK, SB, 0, s2>>>(cnt, incl, boff, rowptr, cursor);
    csr_fill<<<(NE + 255) / 256, 256, 0, s2>>>(src, dst, cursor, csrc);
    cudaEventRecord(evJoin, s2);

    gemm_el_er<128><<<(NN + 127) / 128, 256>>>(x, W1, al1, ar1, h, el, er);

    cudaStreamWaitEvent(0, evJoin, 0);

    gat_aggregate<<<(NN * 32 + 255) / 256, 256>>>(rowptr, csrc, el, er, h, b1, nf);

    gemm_el_er<64><<<(NN + 127) / 128, 256>>>(nf, W2, al2, ar2, h, el, er);
    gat_aggregate<<<(NN * 32 + 255) / 256, 256>>>(rowptr, csrc, el, er, h, b2, nf2);

    gemm_el_er<64><<<(NN + 127) / 128, 256>>>(nf2, W3, al3, ar3, h, el, er);
    gat_aggregate<<<(NN * 32 + 255) / 256, 256>>>(rowptr, csrc, el, er, h, b3, out);
}

// round 9
// speedup vs baseline: 1.1235x; 1.0280x over previous
#include <cuda_runtime.h>
#include <cuda_fp16.h>
#include <cuda_bf16.h>

#define NN 100000
#define NE 1600000
#define HF 64
#define FULL 0xFFFFFFFFu

#define SB   512
#define NBLK ((NN + SB - 1) / SB)   // 196

// ---------------- scratch (device globals; no allocation allowed) ----------
__device__ __half g_h [NN * HF];   // h = x@W in fp16 (halves gather traffic)
__device__ float g_nf [NN * HF];
__device__ float g_nf2[NN * HF];
__device__ float g_el [NN];
__device__ float g_er [NN];
// CSR-by-dst
__device__ int g_cnt   [NN];
__device__ int g_incl  [NN];
__device__ int g_bsum  [NBLK];
__device__ int g_boff  [NBLK];
__device__ int g_rowptr[NN + 1];
__device__ int g_cursor[NN];
__device__ int g_csrc  [NE];

// ============================ CSR build =====================================
__global__ void csr_zero(int* __restrict__ cnt) {
    int i = blockIdx.x * blockDim.x + threadIdx.x;
    if (i < NN) cnt[i] = 0;
}

__global__ void csr_hist(const int* __restrict__ dst, int* __restrict__ cnt) {
    int e = blockIdx.x * blockDim.x + threadIdx.x;
    if (e < NE) atomicAdd(&cnt[dst[e]], 1);
}

__global__ void csr_scan1(const int* __restrict__ cnt, int* __restrict__ incl,
                          int* __restrict__ bsum) {
    __shared__ int wsum[16];
    int tid = threadIdx.x, lane = tid & 31, wid = tid >> 5;
    int i = blockIdx.x * SB + tid;
    int v = (i < NN) ? cnt[i] : 0;
    int x = v;
    #pragma unroll
    for (int o = 1; o < 32; o <<= 1) {
        int t = __shfl_up_sync(FULL, x, o);
        if (lane >= o) x += t;
    }
    if (lane == 31) wsum[wid] = x;
    __syncthreads();
    if (wid == 0) {
        int w = (lane < 16) ? wsum[lane] : 0;
        #pragma unroll
        for (int o = 1; o < 16; o <<= 1) {
            int t = __shfl_up_sync(FULL, w, o);
            if (lane >= o) w += t;
        }
        if (lane < 16) wsum[lane] = w;
    }
    __syncthreads();
    int inc = x + (wid > 0 ? wsum[wid - 1] : 0);
    if (i < NN) incl[i] = inc;
    if (tid == SB - 1) bsum[blockIdx.x] = inc;
}

__global__ void csr_scan2(const int* __restrict__ bsum, int* __restrict__ boff) {
    __shared__ int wsum[8];
    int tid = threadIdx.x, lane = tid & 31, wid = tid >> 5;
    int v = (tid < NBLK) ? bsum[tid] : 0;
    int x = v;
    #pragma unroll
    for (int o = 1; o < 32; o <<= 1) {
        int t = __shfl_up_sync(FULL, x, o);
        if (lane >= o) x += t;
    }
    if (lane == 31) wsum[wid] = x;
    __syncthreads();
    if (wid == 0) {
        int w = (lane < 8) ? wsum[lane] : 0;
        #pragma unroll
        for (int o = 1; o < 8; o <<= 1) {
            int t = __shfl_up_sync(FULL, w, o);
            if (lane >= o) w += t;
        }
        if (lane < 8) wsum[lane] = w;
    }
    __syncthreads();
    int inc = x + (wid > 0 ? wsum[wid - 1] : 0);
    if (tid < NBLK) boff[tid] = inc - v;
}

__global__ void csr_scan3(const int* __restrict__ cnt, const int* __restrict__ incl,
                          const int* __restrict__ boff, int* __restrict__ rowptr,
                          int* __restrict__ cursor) {
    int b = blockIdx.x;
    int i = b * SB + threadIdx.x;
    if (i < NN) {
        int ex = incl[i] - cnt[i] + boff[b];
        rowptr[i] = ex;
        cursor[i] = ex;
    }
    if (i == 0) rowptr[NN] = NE;
}

__global__ void csr_fill(const int* __restrict__ src, const int* __restrict__ dst,
                         int* __restrict__ cursor, int* __restrict__ csrc) {
    int e = blockIdx.x * blockDim.x + threadIdx.x;
    if (e >= NE) return;
    int p = atomicAdd(&cursor[dst[e]], 1);
    csrc[p] = src[e];
}

// ==================== tensor-core GEMM (+ el/er), bf16 3-split ==============
// D = x@W in fp32-grade precision: x=xh+xl, W=Wh+Wl (bf16 splits),
// D = xh*Wh + xh*Wl + xl*Wh. Output h stored as fp16 (half2).

#define KS 32
#define XP (KS + 4)

#define MMA_BF16(C, A0, A1, A2, A3, B0, B1)                              \
    asm volatile(                                                        \
        "mma.sync.aligned.m16n8k16.row.col.f32.bf16.bf16.f32 "           \
        "{%0,%1,%2,%3}, {%4,%5,%6,%7}, {%8,%9}, {%0,%1,%2,%3};\n"        \
        : "+f"(C[0]), "+f"(C[1]), "+f"(C[2]), "+f"(C[3])                 \
        : "r"(A0), "r"(A1), "r"(A2), "r"(A3), "r"(B0), "r"(B1))

__device__ __forceinline__ unsigned ldsm_u32(const __nv_bfloat16* p) {
    return *reinterpret_cast<const unsigned*>(p);
}

template <int K>
__global__ void __launch_bounds__(256)
gemm_el_er(const float* __restrict__ x, const float* __restrict__ W,
           const float* __restrict__ al, const float* __restrict__ ar,
           __half* __restrict__ h, float* __restrict__ el, float* __restrict__ er) {
    __shared__ __nv_bfloat16 sxh[128][XP];
    __shared__ __nv_bfloat16 sxl[128][XP];
    __shared__ __nv_bfloat16 swh[64][XP];
    __shared__ __nv_bfloat16 swl[64][XP];

    int tid = threadIdx.x;
    int warp = tid >> 5, lane = tid & 31;
    int g = lane >> 2, q = lane & 3;
    int base = blockIdx.x * 128;

    float c[8][4];
    #pragma unroll
    for (int nt = 0; nt < 8; nt++)
        #pragma unroll
        for (int i = 0; i < 4; i++) c[nt][i] = 0.0f;

    for (int kc = 0; kc < K; kc += KS) {
        if (kc) __syncthreads();
        #pragma unroll
        for (int it = 0; it < 4; it++) {
            int idx = tid + it * 256;
            int r = idx >> 3, qq = idx & 7;
            int row = base + r;
            float4 v = make_float4(0.f, 0.f, 0.f, 0.f);
            if (row < NN) v = *(const float4*)&x[row * K + kc + qq * 4];
            float vv[4] = {v.x, v.y, v.z, v.w};
            #pragma unroll
            for (int e = 0; e < 4; e++) {
                __nv_bfloat16 hi = __float2bfloat16(vv[e]);
                __nv_bfloat16 lo = __float2bfloat16(vv[e] - __bfloat162float(hi));
                sxh[r][qq * 4 + e] = hi;
                sxl[r][qq * 4 + e] = lo;
            }
        }
        #pragma unroll
        for (int it = 0; it < 2; it++) {
            int idx = tid + it * 256;
            int k = idx >> 4, qq = idx & 15;
            float4 v = *(const float4*)&W[(kc + k) * HF + qq * 4];
            float vv[4] = {v.x, v.y, v.z, v.w};
            #pragma unroll
            for (int e = 0; e < 4; e++) {
                __nv_bfloat16 hi = __float2bfloat16(vv[e]);
                __nv_bfloat16 lo = __float2bfloat16(vv[e] - __bfloat162float(hi));
                swh[qq * 4 + e][k] = hi;
                swl[qq * 4 + e][k] = lo;
            }
        }
        __syncthreads();

        #pragma unroll
        for (int ks = 0; ks < KS / 16; ks++) {
            int k16 = ks * 16;
            int r1 = warp * 16 + g;
            int ka = k16 + q * 2;
            unsigned ah0 = ldsm_u32(&sxh[r1][ka]);
            unsigned ah1 = ldsm_u32(&sxh[r1 + 8][ka]);
            unsigned ah2 = ldsm_u32(&sxh[r1][ka + 8]);
            unsigned ah3 = ldsm_u32(&sxh[r1 + 8][ka + 8]);
            unsigned alo0 = ldsm_u32(&sxl[r1][ka]);
            unsigned alo1 = ldsm_u32(&sxl[r1 + 8][ka]);
            unsigned alo2 = ldsm_u32(&sxl[r1][ka + 8]);
            unsigned alo3 = ldsm_u32(&sxl[r1 + 8][ka + 8]);
            #pragma unroll
            for (int nt = 0; nt < 8; nt++) {
                int n = nt * 8 + g;
                unsigned bh0 = ldsm_u32(&swh[n][ka]);
                unsigned bh1 = ldsm_u32(&swh[n][ka + 8]);
                unsigned bl0 = ldsm_u32(&swl[n][ka]);
                unsigned bl1 = ldsm_u32(&swl[n][ka + 8]);
                MMA_BF16(c[nt], ah0, ah1, ah2, ah3, bh0, bh1);
                MMA_BF16(c[nt], ah0, ah1, ah2, ah3, bl0, bl1);
                MMA_BF16(c[nt], alo0, alo1, alo2, alo3, bh0, bh1);
            }
        }
    }

    // epilogue: store h rows (fp16), fused el/er (fp32)
    int gr1 = base + warp * 16 + g;
    int gr2 = gr1 + 8;
    float pel1 = 0.f, per1 = 0.f, pel2 = 0.f, per2 = 0.f;
    #pragma unroll
    for (int nt = 0; nt < 8; nt++) {
        int col = nt * 8 + q * 2;
        float2 a2 = *(const float2*)&al[col];
        float2 r2 = *(const float2*)&ar[col];
        pel1 += c[nt][0] * a2.x + c[nt][1] * a2.y;
        per1 += c[nt][0] * r2.x + c[nt][1] * r2.y;
        pel2 += c[nt][2] * a2.x + c[nt][3] * a2.y;
        per2 += c[nt][2] * r2.x + c[nt][3] * r2.y;
        if (gr1 < NN) *(__half2*)&h[gr1 * HF + col] =
            __floats2half2_rn(c[nt][0], c[nt][1]);
        if (gr2 < NN) *(__half2*)&h[gr2 * HF + col] =
            __floats2half2_rn(c[nt][2], c[nt][3]);
    }
    #pragma unroll
    for (int o = 1; o <= 2; o <<= 1) {
        pel1 += __shfl_xor_sync(FULL, pel1, o);
        per1 += __shfl_xor_sync(FULL, per1, o);
        pel2 += __shfl_xor_sync(FULL, pel2, o);
        per2 += __shfl_xor_sync(FULL, per2, o);
    }
    if (q == 0) {
        if (gr1 < NN) { el[gr1] = pel1; er[gr1] = per1; }
        if (gr2 < NN) { el[gr2] = pel2; er[gr2] = per2; }
    }
}

// ============== fused per-node softmax + aggregate + bias + relu ============
// Warp per dst node; fp16 h gather (half2/lane), 4 accumulator pairs (MLP 4).
__global__ void __launch_bounds__(256)
gat_aggregate(const int* __restrict__ rowptr, const int* __restrict__ csrc,
              const float* __restrict__ el, const float* __restrict__ er,
              const __half* __restrict__ h, const float* __restrict__ b,
              float* __restrict__ y) {
    int gwarp = (blockIdx.x * blockDim.x + threadIdx.x) >> 5;
    if (gwarp >= NN) return;
    int lane = threadIdx.x & 31;

    int beg = rowptr[gwarp], end = rowptr[gwarp + 1];
    float erd = er[gwarp];

    float m = -__int_as_float(0x7F800000);
    float s = 0.0f;
    float aA0 = 0.f, aA1 = 0.f, aB0 = 0.f, aB1 = 0.f;
    float aC0 = 0.f, aC1 = 0.f, aD0 = 0.f, aD1 = 0.f;
    int c = 2 * lane;

    for (int base = beg; base < end; base += 32) {
        int idx = base + lane;
        bool valid = idx < end;
        int sn = valid ? csrc[idx] : 0;
        float v;
        if (valid) {
            v = el[sn] + erd;
            v = v > 0.0f ? v : 0.2f * v;
        } else {
            v = -__int_as_float(0x7F800000);
        }
        float gm = v;
        #pragma unroll
        for (int o = 16; o > 0; o >>= 1)
            gm = fmaxf(gm, __shfl_xor_sync(FULL, gm, o));
        float mnew = fmaxf(m, gm);
        float scale = __expf(m - mnew);
        s *= scale;
        aA0 *= scale; aA1 *= scale; aB0 *= scale; aB1 *= scale;
        aC0 *= scale; aC1 *= scale; aD0 *= scale; aD1 *= scale;
        m = mnew;

        float w = valid ? __expf(v - mnew) : 0.0f;
        float ws = w;
        #pragma unroll
        for (int o = 16; o > 0; o >>= 1)
            ws += __shfl_xor_sync(FULL, ws, o);
        s += ws;

        int cnt = end - base; if (cnt > 32) cnt = 32;
        int j = 0;
        for (; j + 3 < cnt; j += 4) {
            int   s0 = __shfl_sync(FULL, sn, j);
            int   s1 = __shfl_sync(FULL, sn, j + 1);
            int   s2 = __shfl_sync(FULL, sn, j + 2);
            int   s3 = __shfl_sync(FULL, sn, j + 3);
            float w0 = __shfl_sync(FULL, w, j);
            float w1 = __shfl_sync(FULL, w, j + 1);
            float w2 = __shfl_sync(FULL, w, j + 2);
            float w3 = __shfl_sync(FULL, w, j + 3);
            float2 h0 = __half22float2(*(const __half2*)&h[s0 * HF + c]);
            float2 h1 = __half22float2(*(const __half2*)&h[s1 * HF + c]);
            float2 h2 = __half22float2(*(const __half2*)&h[s2 * HF + c]);
            float2 h3 = __half22float2(*(const __half2*)&h[s3 * HF + c]);
            aA0 = fmaf(w0, h0.x, aA0); aA1 = fmaf(w0, h0.y, aA1);
            aB0 = fmaf(w1, h1.x, aB0); aB1 = fmaf(w1, h1.y, aB1);
            aC0 = fmaf(w2, h2.x, aC0); aC1 = fmaf(w2, h2.y, aC1);
            aD0 = fmaf(w3, h3.x, aD0); aD1 = fmaf(w3, h3.y, aD1);
        }
        for (; j < cnt; j++) {
            int   s0 = __shfl_sync(FULL, sn, j);
            float w0 = __shfl_sync(FULL, w, j);
            float2 h0 = __half22float2(*(const __half2*)&h[s0 * HF + c]);
            aA0 = fmaf(w0, h0.x, aA0); aA1 = fmaf(w0, h0.y, aA1);
        }
    }

    float inv = (end > beg) ? __fdividef(1.0f, s) : 0.0f;
    float o0 = ((aA0 + aB0) + (aC0 + aD0)) * inv + b[c];
    float o1 = ((aA1 + aB1) + (aC1 + aD1)) * inv + b[c + 1];
    o0 = o0 > 0.0f ? o0 : 0.0f;
    o1 = o1 > 0.0f ? o1 : 0.0f;
    *(float2*)&y[gwarp * HF + c] = make_float2(o0, o1);
}

// ============================ host driver ===================================
extern "C" void kernel_launch(void* const* d_in, const int* in_sizes, int n_in,
                              void* d_out, int out_size) {
    const float* x   = (const float*)d_in[0];
    const int*   src = (const int*)  d_in[1];
    const int*   dst = (const int*)  d_in[2];
    const float* W1  = (const float*)d_in[3];
    const float* al1 = (const float*)d_in[4];
    const float* ar1 = (const float*)d_in[5];
    const float* b1  = (const float*)d_in[6];
    const float* W2  = (const float*)d_in[7];
    const float* al2 = (const float*)d_in[8];
    const float* ar2 = (const float*)d_in[9];
    const float* b2  = (const float*)d_in[10];
    const float* W3  = (const float*)d_in[11];
    const float* al3 = (const float*)d_in[12];
    const float* ar3 = (const float*)d_in[13];
    const float* b3  = (const float*)d_in[14];
    float* out = (float*)d_out;

    __half* h;
    float *nf, *nf2, *el, *er;
    int *cnt, *incl, *bsum, *boff, *rowptr, *cursor, *csrc;
    cudaGetSymbolAddress((void**)&h,      g_h);
    cudaGetSymbolAddress((void**)&nf,     g_nf);
    cudaGetSymbolAddress((void**)&nf2,    g_nf2);
    cudaGetSymbolAddress((void**)&el,     g_el);
    cudaGetSymbolAddress((void**)&er,     g_er);
    cudaGetSymbolAddress((void**)&cnt,    g_cnt);
    cudaGetSymbolAddress((void**)&incl,   g_incl);
    cudaGetSymbolAddress((void**)&bsum,   g_bsum);
    cudaGetSymbolAddress((void**)&boff,   g_boff);
    cudaGetSymbolAddress((void**)&rowptr, g_rowptr);
    cudaGetSymbolAddress((void**)&cursor, g_cursor);
    cudaGetSymbolAddress((void**)&csrc,   g_csrc);

    static cudaStream_t s2 = nullptr;
    static cudaEvent_t evFork = nullptr, evJoin = nullptr;
    if (!s2) {
        cudaStreamCreateWithFlags(&s2, cudaStreamNonBlocking);
        cudaEventCreateWithFlags(&evFork, cudaEventDisableTiming);
        cudaEventCreateWithFlags(&evJoin, cudaEventDisableTiming);
    }

    // ---- fork: CSR build on s2, layer-1 GEMM on main stream ----
    cudaEventRecord(evFork, 0);
    cudaStreamWaitEvent(s2, evFork, 0);
    csr_zero<<<(NN + 255) / 256, 256, 0, s2>>>(cnt);
    csr_hist<<<(NE + 255) / 256, 256, 0, s2>>>(dst, cnt);
    csr_scan1<<<NBLK, SB, 0, s2>>>(cnt, incl, bsum);
    csr_scan2<<<1, 256, 0, s2>>>(bsum, boff);
    csr_scan3<<<NBLK, SB, 0, s2>>>(cnt, incl, boff, rowptr, cursor);
    csr_fill<<<(NE + 255) / 256, 256, 0, s2>>>(src, dst, cursor, csrc);
    cudaEventRecord(evJoin, s2);

    gemm_el_er<128><<<(NN + 127) / 128, 256>>>(x, W1, al1, ar1, h, el, er);

    cudaStreamWaitEvent(0, evJoin, 0);

    gat_aggregate<<<(NN * 32 + 255) / 256, 256>>>(rowptr, csrc, el, er, h, b1, nf);

    gemm_el_er<64><<<(NN + 127) / 128, 256>>>(nf, W2, al2, ar2, h, el, er);
    gat_aggregate<<<(NN * 32 + 255) / 256, 256>>>(rowptr, csrc, el, er, h, b2, nf2);

    gemm_el_er<64><<<(NN + 127) / 128, 256>>>(nf2, W3, al3, ar3, h, el, er);
    gat_aggregate<<<(NN * 32 + 255) / 256, 256>>>(rowptr, csrc, el, er, h, b3, out);
}